// round 3
// baseline (speedup 1.0000x reference)
#include <cuda_runtime.h>

#define NN 20000
#define NE 320000
#define SQRT3F 1.7320508075688772f
#define INV_NORM (1.0f/319999.0f)

// ---------------- persistent device state (no allocs allowed) ----------------
__device__ __align__(16) float g_s[NN*16];      // node scalars
__device__ __align__(16) float g_v[NN*3];       // node vector (positions)
__device__ __align__(16) float g_accS[NN*16];   // sum of scalar messages
__device__ __align__(16) float g_accV[NN*48];   // sum of vector messages [16][3]
__device__ __align__(16) float g_accAv[NN*3];   // sum of edge attr vectors
__device__ __align__(16) float g_accCnt[NN];    // edge counts

__device__ __forceinline__ float sigmoidf_(float x){
    return 1.0f/(1.0f+__expf(-x));
}
// jax.nn.gelu default (approximate=True): 0.5x(1+tanh(sqrt(2/pi)(x+0.044715x^3)))
__device__ __forceinline__ float geluf_(float x){
    float t = 0.7978845608028654f*(x + 0.044715f*x*x*x);
    float e = __expf(2.0f*t);
    float th = 1.0f - 2.0f/(e+1.0f);   // robust tanh: ->1 / ->-1 at extremes
    return 0.5f*x*(1.0f+th);
}

// ---------------- init / zero / pack ----------------
__global__ void init_kernel(const float* __restrict__ s_in, const float* __restrict__ v_in){
    int i = blockIdx.x*256 + threadIdx.x;
    if (i < NN*16) g_s[i] = s_in[i];
    if (i < NN*3)  g_v[i] = v_in[i];
}

__global__ void zero_kernel(){
    int i = blockIdx.x*256 + threadIdx.x;
    if (i < NN*48) g_accV[i]   = 0.f;
    if (i < NN*16) g_accS[i]   = 0.f;
    if (i < NN*3)  g_accAv[i]  = 0.f;
    if (i < NN)    g_accCnt[i] = 0.f;
}

__global__ void pack_kernel(float* __restrict__ out){
    int n = blockIdx.x*256 + threadIdx.x;
    if (n >= NN) return;
    #pragma unroll
    for (int p=0;p<16;p++) out[n*19+p] = g_s[n*16+p];
    out[n*19+16] = g_v[n*3+0];
    out[n*19+17] = g_v[n*3+1];
    out[n*19+18] = g_v[n*3+2];
}

// ---------------- edge kernel: 2x TensorProductLinearGate + atomic aggregate ----------------
__global__ void __launch_bounds__(128) edge_kernel(
    const int* __restrict__ senders, const int* __restrict__ receivers,
    const float* __restrict__ Ws0, const float* __restrict__ bs0, const float* __restrict__ Wv0,
    const float* __restrict__ Ws1, const float* __restrict__ bs1, const float* __restrict__ Wv1)
{
    __shared__ __align__(16) float sWs0[34*32];
    __shared__ __align__(16) float sWv0[34*16];
    __shared__ __align__(16) float sWs1[32*32];
    __shared__ __align__(16) float sWv1[32*16];
    __shared__ __align__(16) float sbs0[32];
    __shared__ __align__(16) float sbs1[32];
    int tid = threadIdx.x;
    for (int i=tid;i<34*32;i+=128) sWs0[i]=Ws0[i];
    for (int i=tid;i<34*16;i+=128) sWv0[i]=Wv0[i];
    for (int i=tid;i<32*32;i+=128) sWs1[i]=Ws1[i];
    for (int i=tid;i<32*16;i+=128) sWv1[i]=Wv1[i];
    if (tid<32){ sbs0[tid]=bs0[tid]; sbs1[tid]=bs1[tid]; }
    __syncthreads();

    int e = blockIdx.x*128 + tid;
    if (e >= NE) return;
    int si = senders[e], ri = receivers[e];

    float vsx=g_v[si*3+0], vsy=g_v[si*3+1], vsz=g_v[si*3+2];
    float vrx=g_v[ri*3+0], vry=g_v[ri*3+1], vrz=g_v[ri*3+2];
    float rx=vsx-vrx, ry=vsy-vry, rz=vsz-vrz;
    float nrm = sqrtf(rx*rx+ry*ry+rz*rz) + 1e-8f;
    float kk0 = SQRT3F/nrm;
    float avx=kk0*rx, avy=kk0*ry, avz=kk0*rz;   // a_v = sqrt(3) * rhat

    float xs[32];
    {
        const float4* s4a = (const float4*)(g_s + si*16);
        const float4* s4b = (const float4*)(g_s + ri*16);
        #pragma unroll
        for (int j=0;j<4;j++){ float4 t=s4a[j]; xs[4*j]=t.x; xs[4*j+1]=t.y; xs[4*j+2]=t.z; xs[4*j+3]=t.w; }
        #pragma unroll
        for (int j=0;j<4;j++){ float4 t=s4b[j]; xs[16+4*j]=t.x; xs[16+4*j+1]=t.y; xs[16+4*j+2]=t.z; xs[16+4*j+3]=t.w; }
    }
    float dS = vsx*avx+vsy*avy+vsz*avz;         // dot(v_s, a_v)
    float dR = vrx*avx+vry*avy+vrz*avz;         // dot(v_r, a_v)

    // ---- layer 1: ts=[xs(32), dS, dR]; tv rows: xs[a]*av (32), v_s, v_r ----
    float sl[32], u[16];
    #pragma unroll
    for (int q=0;q<32;q++) sl[q] = sbs0[q] + dS*sWs0[32*32+q] + dR*sWs0[33*32+q];
    #pragma unroll
    for (int q=0;q<16;q++) u[q]=0.f;
    #pragma unroll 4
    for (int a=0;a<32;a++){
        float xa = xs[a];
        const float4* w4 = (const float4*)(sWs0 + a*32);
        #pragma unroll
        for (int k=0;k<8;k++){ float4 w=w4[k];
            sl[4*k]+=xa*w.x; sl[4*k+1]+=xa*w.y; sl[4*k+2]+=xa*w.z; sl[4*k+3]+=xa*w.w; }
        const float4* v4 = (const float4*)(sWv0 + a*16);
        #pragma unroll
        for (int k=0;k<4;k++){ float4 w=v4[k];
            u[4*k]+=xa*w.x; u[4*k+1]+=xa*w.y; u[4*k+2]+=xa*w.z; u[4*k+3]+=xa*w.w; }
    }
    float ms[16], mvx[16], mvy[16], mvz[16];
    #pragma unroll
    for (int q=0;q<16;q++){
        float g   = sigmoidf_(sl[q]);
        float w32 = sWv0[32*16+q], w33 = sWv0[33*16+q];
        mvx[q] = (avx*u[q] + vsx*w32 + vrx*w33)*g;
        mvy[q] = (avy*u[q] + vsy*w32 + vry*w33)*g;
        mvz[q] = (avz*u[q] + vsz*w32 + vrz*w33)*g;
        ms[q]  = geluf_(sl[16+q]);
    }

    // ---- layer 2: ts=[ms(16), dot(mv,av)(16)]; tv rows: ms[p]*av (16), mv (16) ----
    float s2[32], u2[16];
    #pragma unroll
    for (int q=0;q<32;q++) s2[q]=sbs1[q];
    #pragma unroll
    for (int q=0;q<16;q++) u2[q]=0.f;
    #pragma unroll 2
    for (int p=0;p<16;p++){
        float m  = ms[p];
        float d2 = mvx[p]*avx+mvy[p]*avy+mvz[p]*avz;
        const float4* w4  = (const float4*)(sWs1 + p*32);
        const float4* w4b = (const float4*)(sWs1 + (16+p)*32);
        #pragma unroll
        for (int k=0;k<8;k++){ float4 w=w4[k], wb=w4b[k];
            s2[4*k]  += m*w.x + d2*wb.x;
            s2[4*k+1]+= m*w.y + d2*wb.y;
            s2[4*k+2]+= m*w.z + d2*wb.z;
            s2[4*k+3]+= m*w.w + d2*wb.w; }
        const float4* v4 = (const float4*)(sWv1 + p*16);
        #pragma unroll
        for (int k=0;k<4;k++){ float4 w=v4[k];
            u2[4*k]+=m*w.x; u2[4*k+1]+=m*w.y; u2[4*k+2]+=m*w.z; u2[4*k+3]+=m*w.w; }
    }

    float* accS = g_accS + ri*16;
    float* accV = g_accV + ri*48;
    for (int q=0;q<16;q++){
        float g  = sigmoidf_(s2[q]);
        float vx = avx*u2[q], vy = avy*u2[q], vz = avz*u2[q];
        #pragma unroll
        for (int p=0;p<16;p++){
            float w = sWv1[(16+p)*16+q];
            vx += mvx[p]*w; vy += mvy[p]*w; vz += mvz[p]*w;
        }
        atomicAdd(accV+q*3+0, vx*g);
        atomicAdd(accV+q*3+1, vy*g);
        atomicAdd(accV+q*3+2, vz*g);
        atomicAdd(accS+q, geluf_(s2[16+q]));
    }
    atomicAdd(g_accAv+ri*3+0, avx);
    atomicAdd(g_accAv+ri*3+1, avy);
    atomicAdd(g_accAv+ri*3+2, avz);
    atomicAdd(g_accCnt+ri, 1.0f);
}

// ---------------- node kernel: 2x TPLG blocks (289->17) + final linear + residual ----------------
__global__ void __launch_bounds__(128) node_kernel(
    const float* __restrict__ nWs, const float* __restrict__ nbs, const float* __restrict__ nWv,
    const float* __restrict__ fWs, const float* __restrict__ fbs, const float* __restrict__ fWv)
{
    // weight rows padded 17 -> 18 floats (8B-aligned float2 loads)
    __shared__ __align__(16) float sW[2*289*18];
    __shared__ __align__(16) float sV[2*289];
    __shared__ __align__(16) float sB[2*17];
    __shared__ __align__(16) float sF[256];
    __shared__ __align__(16) float sFb[16];
    __shared__ float sFv[1];
    int tid = threadIdx.x;
    for (int i=tid;i<2*289*17;i+=128){
        int b = i/(289*17); int r = i - b*289*17; int p = r/17; int q = r - p*17;
        sW[b*289*18 + p*18 + q] = nWs[i];
    }
    for (int i=tid;i<2*289;i+=128) sV[i]=nWv[i];
    if (tid<34) sB[tid]=nbs[tid];
    for (int i=tid;i<256;i+=128) sF[i]=fWs[i];
    if (tid<16) sFb[tid]=fbs[tid];
    if (tid==0) sFv[0]=fWv[0];
    __syncthreads();

    int n = blockIdx.x*128 + tid;
    if (n >= NN) return;

    float cnt = g_accCnt[n];
    float fsc = INV_NORM / fmaxf(cnt,1.0f);
    float ys[17];
    #pragma unroll
    for (int c=0;c<16;c++) ys[c] = g_accS[n*16+c]*fsc;
    ys[16] = (cnt>0.f) ? INV_NORM : 0.f;        // seg_mean(ones)*inv

    float nsv[16];
    #pragma unroll
    for (int a=0;a<16;a++) nsv[a]=g_s[n*16+a];
    float nvx=g_v[n*3+0], nvy=g_v[n*3+1], nvz=g_v[n*3+2];

    #pragma unroll 1
    for (int b=0;b<2;b++){
        const float* Wb = sW + b*289*18;
        const float* Vb = sV + b*289;
        float sl[17];
        #pragma unroll
        for (int q=0;q<17;q++) sl[q]=sB[b*17+q];
        float wv[17];
        #pragma unroll
        for (int d=0;d<17;d++) wv[d]=0.f;

        // ss rows: ts[a*17+c] = nsv[a]*ys[c] ; sv rows share index (a,d)
        for (int a=0;a<16;a++){
            float na = nsv[a];
            #pragma unroll
            for (int c=0;c<17;c++){
                float t = na*ys[c];
                const float2* wr = (const float2*)(Wb + (a*17+c)*18);
                #pragma unroll
                for (int k=0;k<8;k++){ float2 w=wr[k]; sl[2*k]+=t*w.x; sl[2*k+1]+=t*w.y; }
                sl[16] += t*Wb[(a*17+c)*18+16];
                wv[c]  += na*Vb[a*17+c];        // c doubles as d for the sv rows
            }
        }

        // vv rows (272+d): t = dot(nv, yv[d]); also fold vector output sum yv[d]*wv[d]
        float vx=0.f, vy=0.f, vz=0.f;
        #pragma unroll
        for (int d=0;d<17;d++){
            float yx,yy,yz;
            if (d<16){ yx=g_accV[n*48+d*3+0]*fsc; yy=g_accV[n*48+d*3+1]*fsc; yz=g_accV[n*48+d*3+2]*fsc; }
            else     { yx=g_accAv[n*3+0]*fsc;     yy=g_accAv[n*3+1]*fsc;     yz=g_accAv[n*3+2]*fsc; }
            float t = nvx*yx+nvy*yy+nvz*yz;
            const float2* wr = (const float2*)(Wb + (272+d)*18);
            #pragma unroll
            for (int k=0;k<8;k++){ float2 w=wr[k]; sl[2*k]+=t*w.x; sl[2*k+1]+=t*w.y; }
            sl[16] += t*Wb[(272+d)*18+16];
            vx += yx*wv[d]; vy += yy*wv[d]; vz += yz*wv[d];
        }
        // vs rows (272+c) of tv: nv * ys[c] * Wv[272+c]
        float sc=0.f;
        #pragma unroll
        for (int c=0;c<17;c++) sc += ys[c]*Vb[272+c];
        vx += nvx*sc; vy += nvy*sc; vz += nvz*sc;

        float g = sigmoidf_(sl[0]);
        #pragma unroll
        for (int p=0;p<16;p++) nsv[p] = geluf_(sl[1+p]);
        nvx = vx*g; nvy = vy*g; nvz = vz*g;
    }

    // final linear back to irreps_in + residual
    float out[16];
    #pragma unroll
    for (int p=0;p<16;p++){
        float acc = g_s[n*16+p] + sFb[p];
        #pragma unroll
        for (int a=0;a<16;a++) acc += nsv[a]*sF[a*16+p];
        out[p]=acc;
    }
    #pragma unroll
    for (int p=0;p<16;p++) g_s[n*16+p]=out[p];
    float fv = sFv[0];
    g_v[n*3+0] += nvx*fv;
    g_v[n*3+1] += nvy*fv;
    g_v[n*3+2] += nvz*fv;
}

// ---------------- launch ----------------
extern "C" void kernel_launch(void* const* d_in, const int* in_sizes, int n_in,
                              void* d_out, int out_size)
{
    const float* node_s   = (const float*)d_in[0];
    const float* node_p   = (const float*)d_in[1];
    const int*   senders  = (const int*)d_in[2];
    const int*   receivers= (const int*)d_in[3];
    const float* eWs0 = (const float*)d_in[4];
    const float* ebs0 = (const float*)d_in[5];
    const float* eWv0 = (const float*)d_in[6];
    const float* eWs1 = (const float*)d_in[7];
    const float* ebs1 = (const float*)d_in[8];
    const float* eWv1 = (const float*)d_in[9];
    const float* nWs  = (const float*)d_in[10];
    const float* nbs  = (const float*)d_in[11];
    const float* nWv  = (const float*)d_in[12];
    const float* fWs  = (const float*)d_in[13];
    const float* fbs  = (const float*)d_in[14];
    const float* fWv  = (const float*)d_in[15];

    init_kernel<<<(NN*16+255)/256,256>>>(node_s, node_p);
    for (int t=0;t<3;t++){
        zero_kernel<<<(NN*48+255)/256,256>>>();
        edge_kernel<<<(NE+127)/128,128>>>(senders, receivers,
            eWs0 + t*34*32, ebs0 + t*32, eWv0 + t*34*16,
            eWs1 + t*32*32, ebs1 + t*32, eWv1 + t*32*16);
        node_kernel<<<(NN+127)/128,128>>>(
            nWs + t*2*289*17, nbs + t*2*17, nWv + t*2*289,
            fWs + t*256, fbs + t*16, fWv + t);
    }
    pack_kernel<<<(NN+255)/256,256>>>((float*)d_out);
}

// round 5
// speedup vs baseline: 1.3068x; 1.3068x over previous
#include <cuda_runtime.h>

#define NN 20000
#define NE 320000
#define SQRT3F 1.7320508075688772f
#define INV_NORM (1.0f/319999.0f)

typedef unsigned long long u64;

// ---------------- persistent device state (no allocs allowed) ----------------
__device__ __align__(16) float g_s[NN*16];      // node scalars
__device__ __align__(16) float g_v[NN*3];       // node vector (positions)
__device__ __align__(16) float g_accS[NN*16];   // sum of scalar messages
__device__ __align__(16) float g_accV[NN*48];   // sum of vector messages [16][3]
__device__ __align__(16) float g_accAv[NN*3];   // sum of edge attr vectors
__device__ __align__(16) float g_cnt[NN];       // edge counts (constant across steps)

// ---------------- f32x2 packed-math helpers (sm_103a dual FMA pipe) ----------
__device__ __forceinline__ u64 pk2(float a, float b){ u64 r; asm("mov.b64 %0,{%1,%2};":"=l"(r):"f"(a),"f"(b)); return r; }
__device__ __forceinline__ u64 bc2(float a){ return pk2(a,a); }
__device__ __forceinline__ void upk2(u64 v, float&a, float&b){ asm("mov.b64 {%0,%1},%2;":"=f"(a),"=f"(b):"l"(v)); }
__device__ __forceinline__ void fma2_(u64&d, u64 a, u64 b){ asm("fma.rn.f32x2 %0,%1,%2,%0;":"+l"(d):"l"(a),"l"(b)); }
__device__ __forceinline__ u64 mul2_(u64 a, u64 b){ u64 r; asm("mul.rn.f32x2 %0,%1,%2;":"=l"(r):"l"(a),"l"(b)); return r; }

__device__ __forceinline__ float sigmoidf_(float x){
    return 1.0f/(1.0f+__expf(-x));
}
// jax.nn.gelu default (approximate=True): 0.5x(1+tanh(sqrt(2/pi)(x+0.044715x^3)))
__device__ __forceinline__ float geluf_(float x){
    float t = 0.7978845608028654f*(x + 0.044715f*x*x*x);
    float e = __expf(2.0f*t);
    float th = 1.0f - 2.0f/(e+1.0f);   // robust tanh: ->1 / ->-1 at extremes
    return 0.5f*x*(1.0f+th);
}

// ---------------- init / count / zero / pack ----------------
__global__ void init_kernel(const float* __restrict__ s_in, const float* __restrict__ v_in){
    int i = blockIdx.x*256 + threadIdx.x;
    if (i < NN*16) g_s[i] = s_in[i];
    if (i < NN*3)  g_v[i] = v_in[i];
    if (i < NN)    g_cnt[i] = 0.f;
}

__global__ void count_kernel(const int* __restrict__ receivers){
    int e = blockIdx.x*256 + threadIdx.x;
    if (e < NE) atomicAdd(g_cnt + receivers[e], 1.0f);
}

__global__ void zero_kernel(){
    int i = blockIdx.x*256 + threadIdx.x;
    if (i < NN*48) g_accV[i]   = 0.f;
    if (i < NN*16) g_accS[i]   = 0.f;
    if (i < NN*3)  g_accAv[i]  = 0.f;
}

__global__ void pack_kernel(float* __restrict__ out){
    int n = blockIdx.x*256 + threadIdx.x;
    if (n >= NN) return;
    #pragma unroll
    for (int p=0;p<16;p++) out[n*19+p] = g_s[n*16+p];
    out[n*19+16] = g_v[n*3+0];
    out[n*19+17] = g_v[n*3+1];
    out[n*19+18] = g_v[n*3+2];
}

// ---------------- edge kernel: 2x TensorProductLinearGate + atomic aggregate ----------------
__global__ void __launch_bounds__(128) edge_kernel(
    const int* __restrict__ senders, const int* __restrict__ receivers,
    const float* __restrict__ Ws0, const float* __restrict__ bs0, const float* __restrict__ Wv0,
    const float* __restrict__ Ws1, const float* __restrict__ bs1, const float* __restrict__ Wv1)
{
    __shared__ __align__(16) float sWs0[34*32];
    __shared__ __align__(16) float sWv0[34*16];
    __shared__ __align__(16) float sWs1[32*32];
    __shared__ __align__(16) float sWv1[32*16];
    __shared__ __align__(16) float sbs0[32];
    __shared__ __align__(16) float sbs1[32];
    int tid = threadIdx.x;
    for (int i=tid;i<34*32;i+=128) sWs0[i]=Ws0[i];
    for (int i=tid;i<34*16;i+=128) sWv0[i]=Wv0[i];
    for (int i=tid;i<32*32;i+=128) sWs1[i]=Ws1[i];
    for (int i=tid;i<32*16;i+=128) sWv1[i]=Wv1[i];
    if (tid<32){ sbs0[tid]=bs0[tid]; sbs1[tid]=bs1[tid]; }
    __syncthreads();

    int e = blockIdx.x*128 + tid;
    if (e >= NE) return;
    int si = senders[e], ri = receivers[e];

    float vsx=g_v[si*3+0], vsy=g_v[si*3+1], vsz=g_v[si*3+2];
    float vrx=g_v[ri*3+0], vry=g_v[ri*3+1], vrz=g_v[ri*3+2];
    float rx=vsx-vrx, ry=vsy-vry, rz=vsz-vrz;
    float nrm = sqrtf(rx*rx+ry*ry+rz*rz) + 1e-8f;
    float kk0 = SQRT3F/nrm;
    float avx=kk0*rx, avy=kk0*ry, avz=kk0*rz;   // a_v = sqrt(3) * rhat

    float xs[32];
    {
        const float4* s4a = (const float4*)(g_s + si*16);
        const float4* s4b = (const float4*)(g_s + ri*16);
        #pragma unroll
        for (int j=0;j<4;j++){ float4 t=s4a[j]; xs[4*j]=t.x; xs[4*j+1]=t.y; xs[4*j+2]=t.z; xs[4*j+3]=t.w; }
        #pragma unroll
        for (int j=0;j<4;j++){ float4 t=s4b[j]; xs[16+4*j]=t.x; xs[16+4*j+1]=t.y; xs[16+4*j+2]=t.z; xs[16+4*j+3]=t.w; }
    }
    float dS = vsx*avx+vsy*avy+vsz*avz;         // dot(v_s, a_v)
    float dR = vrx*avx+vry*avy+vrz*avz;         // dot(v_r, a_v)

    // ---- layer 1 (packed q-pairs): ts=[xs(32), dS, dR]; tv rows: xs[a]*av (32), v_s, v_r ----
    u64 sl2[16], ua[8];
    {
        u64 dS2 = bc2(dS), dR2 = bc2(dR);
        const u64* b0  = (const u64*)sbs0;
        const u64* w32 = (const u64*)(sWs0 + 32*32);
        const u64* w33 = (const u64*)(sWs0 + 33*32);
        #pragma unroll
        for (int k=0;k<16;k++){ sl2[k]=b0[k]; fma2_(sl2[k],dS2,w32[k]); fma2_(sl2[k],dR2,w33[k]); }
        #pragma unroll
        for (int k=0;k<8;k++) ua[k]=0ull;
    }
    #pragma unroll 4
    for (int a=0;a<32;a++){
        u64 xa2 = bc2(xs[a]);
        const u64* w = (const u64*)(sWs0 + a*32);
        #pragma unroll
        for (int k=0;k<16;k++) fma2_(sl2[k], xa2, w[k]);
        const u64* v = (const u64*)(sWv0 + a*16);
        #pragma unroll
        for (int k=0;k<8;k++) fma2_(ua[k], xa2, v[k]);
    }
    float sl[32], u[16];
    #pragma unroll
    for (int k=0;k<16;k++) upk2(sl2[k], sl[2*k], sl[2*k+1]);
    #pragma unroll
    for (int k=0;k<8;k++)  upk2(ua[k], u[2*k], u[2*k+1]);

    float ms[16], mvx[16], mvy[16], mvz[16];
    #pragma unroll
    for (int q=0;q<16;q++){
        float g   = sigmoidf_(sl[q]);
        float w32 = sWv0[32*16+q], w33 = sWv0[33*16+q];
        mvx[q] = (avx*u[q] + vsx*w32 + vrx*w33)*g;
        mvy[q] = (avy*u[q] + vsy*w32 + vry*w33)*g;
        mvz[q] = (avz*u[q] + vsz*w32 + vrz*w33)*g;
        ms[q]  = geluf_(sl[16+q]);
    }

    // ---- layer 2 (packed): ts=[ms(16), dot(mv,av)(16)]; tv rows: ms[p]*av (16), mv (16) ----
    u64 s22[16], u22[8];
    {
        const u64* b1 = (const u64*)sbs1;
        #pragma unroll
        for (int k=0;k<16;k++) s22[k]=b1[k];
        #pragma unroll
        for (int k=0;k<8;k++)  u22[k]=0ull;
    }
    #pragma unroll 2
    for (int p=0;p<16;p++){
        float m  = ms[p];
        float d2 = mvx[p]*avx + mvy[p]*avy + mvz[p]*avz;
        u64 m2 = bc2(m), dd = bc2(d2);
        const u64* w  = (const u64*)(sWs1 + p*32);
        const u64* wb = (const u64*)(sWs1 + (16+p)*32);
        #pragma unroll
        for (int k=0;k<16;k++){ fma2_(s22[k], m2, w[k]); fma2_(s22[k], dd, wb[k]); }
        const u64* v = (const u64*)(sWv1 + p*16);
        #pragma unroll
        for (int k=0;k<8;k++) fma2_(u22[k], m2, v[k]);
    }
    float s2[32];
    #pragma unroll
    for (int k=0;k<16;k++) upk2(s22[k], s2[2*k], s2[2*k+1]);

    // ---- vector output: v_out[q] = av*u2[q] + sum_p mv[p]*Wv1[16+p][q]  (packed q-pairs) ----
    u64 vxa[8], vya[8], vza[8];
    {
        u64 ax2=bc2(avx), ay2=bc2(avy), az2=bc2(avz);
        #pragma unroll
        for (int k=0;k<8;k++){ vxa[k]=mul2_(ax2,u22[k]); vya[k]=mul2_(ay2,u22[k]); vza[k]=mul2_(az2,u22[k]); }
    }
    #pragma unroll 4
    for (int p=0;p<16;p++){
        u64 mx=bc2(mvx[p]), my=bc2(mvy[p]), mz=bc2(mvz[p]);
        const u64* w2 = (const u64*)(sWv1 + (16+p)*16);
        #pragma unroll
        for (int k=0;k<8;k++){ fma2_(vxa[k],mx,w2[k]); fma2_(vya[k],my,w2[k]); fma2_(vza[k],mz,w2[k]); }
    }

    float* accS = g_accS + ri*16;
    float* accV = g_accV + ri*48;
    #pragma unroll
    for (int k=0;k<8;k++){
        float g0 = sigmoidf_(s2[2*k]);
        float g1 = sigmoidf_(s2[2*k+1]);
        float x0,x1,y0,y1,z0,z1;
        upk2(vxa[k],x0,x1); upk2(vya[k],y0,y1); upk2(vza[k],z0,z1);
        atomicAdd(accV+(2*k)*3+0, x0*g0);
        atomicAdd(accV+(2*k)*3+1, y0*g0);
        atomicAdd(accV+(2*k)*3+2, z0*g0);
        atomicAdd(accV+(2*k+1)*3+0, x1*g1);
        atomicAdd(accV+(2*k+1)*3+1, y1*g1);
        atomicAdd(accV+(2*k+1)*3+2, z1*g1);
        atomicAdd(accS+2*k,   geluf_(s2[16+2*k]));
        atomicAdd(accS+2*k+1, geluf_(s2[16+2*k+1]));
    }
    atomicAdd(g_accAv+ri*3+0, avx);
    atomicAdd(g_accAv+ri*3+1, avy);
    atomicAdd(g_accAv+ri*3+2, avz);
}

// ---------------- node kernel: 2x TPLG blocks (289->17) + final linear + residual ----------------
__global__ void __launch_bounds__(128) node_kernel(
    const float* __restrict__ nWs, const float* __restrict__ nbs, const float* __restrict__ nWv,
    const float* __restrict__ fWs, const float* __restrict__ fbs, const float* __restrict__ fWv)
{
    // weight rows padded 17 -> 18 floats (8B-aligned u64 pair loads)
    __shared__ __align__(16) float sW[2*289*18];
    __shared__ __align__(16) float sV[2*289];
    __shared__ __align__(16) float sB[2*17];
    __shared__ __align__(16) float sF[256];
    __shared__ __align__(16) float sFb[16];
    __shared__ float sFv[1];
    int tid = threadIdx.x;
    for (int i=tid;i<2*289*17;i+=128){
        int b = i/(289*17); int r = i - b*289*17; int p = r/17; int q = r - p*17;
        sW[b*289*18 + p*18 + q] = nWs[i];
    }
    for (int i=tid;i<2*289;i+=128) sV[i]=nWv[i];
    if (tid<34) sB[tid]=nbs[tid];
    for (int i=tid;i<256;i+=128) sF[i]=fWs[i];
    if (tid<16) sFb[tid]=fbs[tid];
    if (tid==0) sFv[0]=fWv[0];
    __syncthreads();

    int n = blockIdx.x*128 + tid;
    if (n >= NN) return;

    float cnt = g_cnt[n];
    float fsc = INV_NORM / fmaxf(cnt,1.0f);
    float ys[17];
    #pragma unroll
    for (int c=0;c<16;c++) ys[c] = g_accS[n*16+c]*fsc;
    ys[16] = (cnt>0.f) ? INV_NORM : 0.f;        // seg_mean(ones)*inv

    float nsv[16];
    #pragma unroll
    for (int a=0;a<16;a++) nsv[a]=g_s[n*16+a];
    float nvx=g_v[n*3+0], nvy=g_v[n*3+1], nvz=g_v[n*3+2];

    #pragma unroll 1
    for (int b=0;b<2;b++){
        const float* Wb = sW + b*289*18;
        const float* Vb = sV + b*289;
        u64 sl2[8];
        float sl16;
        {
            const u64* bb = (const u64*)(sB + b*17);  // b*17 may be odd-offset; load scalar instead
            (void)bb;
            float tmp[17];
            #pragma unroll
            for (int q=0;q<17;q++) tmp[q]=sB[b*17+q];
            #pragma unroll
            for (int k=0;k<8;k++) sl2[k]=pk2(tmp[2*k],tmp[2*k+1]);
            sl16 = tmp[16];
        }
        float wv[17];
        #pragma unroll
        for (int d=0;d<17;d++) wv[d]=0.f;

        // ss rows: ts[a*17+c] = nsv[a]*ys[c] ; sv rows share index (a,d)
        for (int a=0;a<16;a++){
            float na = nsv[a];
            #pragma unroll
            for (int c=0;c<17;c++){
                float t = na*ys[c];
                u64 t2 = bc2(t);
                const u64* wr = (const u64*)(Wb + (a*17+c)*18);
                #pragma unroll
                for (int k=0;k<8;k++) fma2_(sl2[k], t2, wr[k]);
                sl16  += t*Wb[(a*17+c)*18+16];
                wv[c] += na*Vb[a*17+c];        // c doubles as d for the sv rows
            }
        }

        // vv rows (272+d): t = dot(nv, yv[d]); also fold vector output sum yv[d]*wv[d]
        float vx=0.f, vy=0.f, vz=0.f;
        #pragma unroll
        for (int d=0;d<17;d++){
            float yx,yy,yz;
            if (d<16){ yx=g_accV[n*48+d*3+0]*fsc; yy=g_accV[n*48+d*3+1]*fsc; yz=g_accV[n*48+d*3+2]*fsc; }
            else     { yx=g_accAv[n*3+0]*fsc;     yy=g_accAv[n*3+1]*fsc;     yz=g_accAv[n*3+2]*fsc; }
            float t = nvx*yx+nvy*yy+nvz*yz;
            u64 t2 = bc2(t);
            const u64* wr = (const u64*)(Wb + (272+d)*18);
            #pragma unroll
            for (int k=0;k<8;k++) fma2_(sl2[k], t2, wr[k]);
            sl16 += t*Wb[(272+d)*18+16];
            vx += yx*wv[d]; vy += yy*wv[d]; vz += yz*wv[d];
        }
        // vs rows (272+c) of tv: nv * ys[c] * Wv[272+c]
        float sc=0.f;
        #pragma unroll
        for (int c=0;c<17;c++) sc += ys[c]*Vb[272+c];
        vx += nvx*sc; vy += nvy*sc; vz += nvz*sc;

        float sl[16];
        #pragma unroll
        for (int k=0;k<8;k++) upk2(sl2[k], sl[2*k], sl[2*k+1]);
        float g = sigmoidf_(sl[0]);
        #pragma unroll
        for (int p=0;p<15;p++) nsv[p] = geluf_(sl[1+p]);
        nsv[15] = geluf_(sl16);
        nvx = vx*g; nvy = vy*g; nvz = vz*g;
    }

    // final linear back to irreps_in + residual (packed output pairs)
    u64 out2[8];
    {
        const u64* gs2 = (const u64*)(g_s + n*16);
        const u64* fb2 = (const u64*)sFb;
        #pragma unroll
        for (int k=0;k<8;k++){ out2[k]=gs2[k]; fma2_(out2[k], bc2(1.0f), fb2[k]); }
    }
    #pragma unroll
    for (int a=0;a<16;a++){
        u64 na2 = bc2(nsv[a]);
        const u64* w2 = (const u64*)(sF + a*16);
        #pragma unroll
        for (int k=0;k<8;k++) fma2_(out2[k], na2, w2[k]);
    }
    u64* gs2w = (u64*)(g_s + n*16);
    #pragma unroll
    for (int k=0;k<8;k++) gs2w[k]=out2[k];
    float fv = sFv[0];
    g_v[n*3+0] += nvx*fv;
    g_v[n*3+1] += nvy*fv;
    g_v[n*3+2] += nvz*fv;
}

// ---------------- launch ----------------
extern "C" void kernel_launch(void* const* d_in, const int* in_sizes, int n_in,
                              void* d_out, int out_size)
{
    const float* node_s   = (const float*)d_in[0];
    const float* node_p   = (const float*)d_in[1];
    const int*   senders  = (const int*)d_in[2];
    const int*   receivers= (const int*)d_in[3];
    const float* eWs0 = (const float*)d_in[4];
    const float* ebs0 = (const float*)d_in[5];
    const float* eWv0 = (const float*)d_in[6];
    const float* eWs1 = (const float*)d_in[7];
    const float* ebs1 = (const float*)d_in[8];
    const float* eWv1 = (const float*)d_in[9];
    const float* nWs  = (const float*)d_in[10];
    const float* nbs  = (const float*)d_in[11];
    const float* nWv  = (const float*)d_in[12];
    const float* fWs  = (const float*)d_in[13];
    const float* fbs  = (const float*)d_in[14];
    const float* fWv  = (const float*)d_in[15];

    init_kernel<<<(NN*16+255)/256,256>>>(node_s, node_p);
    count_kernel<<<(NE+255)/256,256>>>(receivers);
    for (int t=0;t<3;t++){
        zero_kernel<<<(NN*48+255)/256,256>>>();
        edge_kernel<<<(NE+127)/128,128>>>(senders, receivers,
            eWs0 + t*34*32, ebs0 + t*32, eWv0 + t*34*16,
            eWs1 + t*32*32, ebs1 + t*32, eWv1 + t*32*16);
        node_kernel<<<(NN+127)/128,128>>>(
            nWs + t*2*289*17, nbs + t*2*17, nWv + t*2*289,
            fWs + t*256, fbs + t*16, fWv + t);
    }
    pack_kernel<<<(NN+255)/256,256>>>((float*)d_out);
}

// round 7
// speedup vs baseline: 1.3389x; 1.0246x over previous
#include <cuda_runtime.h>

#define NN 20000
#define NE 320000
#define SQRT3F 1.7320508075688772f
#define INV_NORM (1.0f/319999.0f)

typedef unsigned long long u64;

// ---------------- persistent device state (no allocs allowed) ----------------
__device__ __align__(16) float g_s[NN*16];      // node scalars
__device__ __align__(16) float g_v[NN*3];       // node vector (positions)
__device__ __align__(16) float g_accS[NN*16];   // aggregated scalar messages
__device__ __align__(16) float g_accV[NN*48];   // aggregated vector messages [16][3]
__device__ __align__(16) float g_accAv[NN*3];   // aggregated edge attr vectors
__device__ int g_cnt_i[NN];                     // per-receiver edge counts
__device__ int g_row[NN+1];                     // CSR row offsets (receiver-sorted)
__device__ int g_fill[NN];                      // scatter cursors
__device__ int g_src[NE];                       // senders in receiver-sorted order
__device__ int g_dst[NE];                       // receivers in receiver-sorted order
__device__ float g_msg[(size_t)67*NE];          // channel-major message buffer (~86MB)

// ---------------- f32x2 packed-math helpers (sm_103a dual FMA pipe) ----------
__device__ __forceinline__ u64 pk2(float a, float b){ u64 r; asm("mov.b64 %0,{%1,%2};":"=l"(r):"f"(a),"f"(b)); return r; }
__device__ __forceinline__ u64 bc2(float a){ return pk2(a,a); }
__device__ __forceinline__ void upk2(u64 v, float&a, float&b){ asm("mov.b64 {%0,%1},%2;":"=f"(a),"=f"(b):"l"(v)); }
__device__ __forceinline__ void fma2_(u64&d, u64 a, u64 b){ asm("fma.rn.f32x2 %0,%1,%2,%0;":"+l"(d):"l"(a),"l"(b)); }
__device__ __forceinline__ u64 mul2_(u64 a, u64 b){ u64 r; asm("mul.rn.f32x2 %0,%1,%2;":"=l"(r):"l"(a),"l"(b)); return r; }

__device__ __forceinline__ float sigmoidf_(float x){
    return 1.0f/(1.0f+__expf(-x));
}
// jax.nn.gelu default (approximate=True)
__device__ __forceinline__ float geluf_(float x){
    float t = 0.7978845608028654f*(x + 0.044715f*x*x*x);
    float e = __expf(2.0f*t);
    float th = 1.0f - 2.0f/(e+1.0f);
    return 0.5f*x*(1.0f+th);
}

// ---------------- init / CSR build / pack ----------------
__global__ void init_kernel(const float* __restrict__ s_in, const float* __restrict__ v_in){
    int i = blockIdx.x*256 + threadIdx.x;
    if (i < NN*16) g_s[i] = s_in[i];
    if (i < NN*3)  g_v[i] = v_in[i];
    if (i < NN)    g_cnt_i[i] = 0;
}

__global__ void count_kernel(const int* __restrict__ receivers){
    int e = blockIdx.x*256 + threadIdx.x;
    if (e < NE) atomicAdd(&g_cnt_i[receivers[e]], 1);
}

__global__ void scan_kernel(){
    __shared__ int part[1024];
    int t = threadIdx.x;
    int base = t*20;
    int s = 0;
    if (base < NN){
        #pragma unroll
        for (int i=0;i<20;i++){ int n=base+i; if (n<NN) s += g_cnt_i[n]; }
    }
    part[t]=s; __syncthreads();
    // inclusive scan (Hillis-Steele)
    for (int off=1;off<1024;off<<=1){
        int v = (t>=off)?part[t-off]:0;
        __syncthreads();
        part[t]+=v;
        __syncthreads();
    }
    int excl = (t==0)?0:part[t-1];
    if (base < NN){
        int run = excl;
        #pragma unroll
        for (int i=0;i<20;i++){
            int n=base+i;
            if (n<NN){ g_row[n]=run; g_fill[n]=run; run+=g_cnt_i[n]; }
        }
    }
    if (t==1023) g_row[NN]=part[1023];
}

__global__ void scatter_kernel(const int* __restrict__ senders, const int* __restrict__ receivers){
    int e = blockIdx.x*256 + threadIdx.x;
    if (e >= NE) return;
    int ri = receivers[e];
    int s = atomicAdd(&g_fill[ri], 1);
    g_src[s] = senders[e];
    g_dst[s] = ri;
}

__global__ void pack_kernel(float* __restrict__ out){
    int n = blockIdx.x*256 + threadIdx.x;
    if (n >= NN) return;
    #pragma unroll
    for (int p=0;p<16;p++) out[n*19+p] = g_s[n*16+p];
    out[n*19+16] = g_v[n*3+0];
    out[n*19+17] = g_v[n*3+1];
    out[n*19+18] = g_v[n*3+2];
}

// ---------------- edge kernel: 2x TPLG, coalesced message write ----------------
__global__ void __launch_bounds__(128) edge_kernel(
    const float* __restrict__ Ws0, const float* __restrict__ bs0, const float* __restrict__ Wv0,
    const float* __restrict__ Ws1, const float* __restrict__ bs1, const float* __restrict__ Wv1)
{
    __shared__ __align__(16) float sWs0[34*32];
    __shared__ __align__(16) float sWv0[34*16];
    __shared__ __align__(16) float sWs1[32*32];
    __shared__ __align__(16) float sWv1[32*16];
    __shared__ __align__(16) float sbs0[32];
    __shared__ __align__(16) float sbs1[32];
    int tid = threadIdx.x;
    for (int i=tid;i<34*32;i+=128) sWs0[i]=Ws0[i];
    for (int i=tid;i<34*16;i+=128) sWv0[i]=Wv0[i];
    for (int i=tid;i<32*32;i+=128) sWs1[i]=Ws1[i];
    for (int i=tid;i<32*16;i+=128) sWv1[i]=Wv1[i];
    if (tid<32){ sbs0[tid]=bs0[tid]; sbs1[tid]=bs1[tid]; }
    __syncthreads();

    int s = blockIdx.x*128 + tid;      // slot in receiver-sorted order
    if (s >= NE) return;
    int si = g_src[s], ri = g_dst[s];

    float vsx=g_v[si*3+0], vsy=g_v[si*3+1], vsz=g_v[si*3+2];
    float vrx=g_v[ri*3+0], vry=g_v[ri*3+1], vrz=g_v[ri*3+2];
    float rx=vsx-vrx, ry=vsy-vry, rz=vsz-vrz;
    float nrm = sqrtf(rx*rx+ry*ry+rz*rz) + 1e-8f;
    float kk0 = SQRT3F/nrm;
    float avx=kk0*rx, avy=kk0*ry, avz=kk0*rz;   // a_v = sqrt(3) * rhat

    float xs[32];
    {
        const float4* s4a = (const float4*)(g_s + si*16);
        const float4* s4b = (const float4*)(g_s + ri*16);
        #pragma unroll
        for (int j=0;j<4;j++){ float4 t=s4a[j]; xs[4*j]=t.x; xs[4*j+1]=t.y; xs[4*j+2]=t.z; xs[4*j+3]=t.w; }
        #pragma unroll
        for (int j=0;j<4;j++){ float4 t=s4b[j]; xs[16+4*j]=t.x; xs[16+4*j+1]=t.y; xs[16+4*j+2]=t.z; xs[16+4*j+3]=t.w; }
    }
    float dS = vsx*avx+vsy*avy+vsz*avz;
    float dR = vrx*avx+vry*avy+vrz*avz;

    // ---- layer 1 (packed q-pairs) ----
    u64 sl2[16], ua[8];
    {
        u64 dS2 = bc2(dS), dR2 = bc2(dR);
        const u64* b0  = (const u64*)sbs0;
        const u64* w32 = (const u64*)(sWs0 + 32*32);
        const u64* w33 = (const u64*)(sWs0 + 33*32);
        #pragma unroll
        for (int k=0;k<16;k++){ sl2[k]=b0[k]; fma2_(sl2[k],dS2,w32[k]); fma2_(sl2[k],dR2,w33[k]); }
        #pragma unroll
        for (int k=0;k<8;k++) ua[k]=0ull;
    }
    #pragma unroll 4
    for (int a=0;a<32;a++){
        u64 xa2 = bc2(xs[a]);
        const u64* w = (const u64*)(sWs0 + a*32);
        #pragma unroll
        for (int k=0;k<16;k++) fma2_(sl2[k], xa2, w[k]);
        const u64* v = (const u64*)(sWv0 + a*16);
        #pragma unroll
        for (int k=0;k<8;k++) fma2_(ua[k], xa2, v[k]);
    }
    float sl[32], u[16];
    #pragma unroll
    for (int k=0;k<16;k++) upk2(sl2[k], sl[2*k], sl[2*k+1]);
    #pragma unroll
    for (int k=0;k<8;k++)  upk2(ua[k], u[2*k], u[2*k+1]);

    float ms[16], mvx[16], mvy[16], mvz[16];
    #pragma unroll
    for (int q=0;q<16;q++){
        float g   = sigmoidf_(sl[q]);
        float w32 = sWv0[32*16+q], w33 = sWv0[33*16+q];
        mvx[q] = (avx*u[q] + vsx*w32 + vrx*w33)*g;
        mvy[q] = (avy*u[q] + vsy*w32 + vry*w33)*g;
        mvz[q] = (avz*u[q] + vsz*w32 + vrz*w33)*g;
        ms[q]  = geluf_(sl[16+q]);
    }

    // ---- layer 2 (packed) ----
    u64 s22[16], u22[8];
    {
        const u64* b1 = (const u64*)sbs1;
        #pragma unroll
        for (int k=0;k<16;k++) s22[k]=b1[k];
        #pragma unroll
        for (int k=0;k<8;k++)  u22[k]=0ull;
    }
    #pragma unroll 2
    for (int p=0;p<16;p++){
        float m  = ms[p];
        float d2 = mvx[p]*avx + mvy[p]*avy + mvz[p]*avz;
        u64 m2 = bc2(m), dd = bc2(d2);
        const u64* w  = (const u64*)(sWs1 + p*32);
        const u64* wb = (const u64*)(sWs1 + (16+p)*32);
        #pragma unroll
        for (int k=0;k<16;k++){ fma2_(s22[k], m2, w[k]); fma2_(s22[k], dd, wb[k]); }
        const u64* v = (const u64*)(sWv1 + p*16);
        #pragma unroll
        for (int k=0;k<8;k++) fma2_(u22[k], m2, v[k]);
    }
    float s2[32];
    #pragma unroll
    for (int k=0;k<16;k++) upk2(s22[k], s2[2*k], s2[2*k+1]);

    // ---- vector output ----
    u64 vxa[8], vya[8], vza[8];
    {
        u64 ax2=bc2(avx), ay2=bc2(avy), az2=bc2(avz);
        #pragma unroll
        for (int k=0;k<8;k++){ vxa[k]=mul2_(ax2,u22[k]); vya[k]=mul2_(ay2,u22[k]); vza[k]=mul2_(az2,u22[k]); }
    }
    #pragma unroll 4
    for (int p=0;p<16;p++){
        u64 mx=bc2(mvx[p]), my=bc2(mvy[p]), mz=bc2(mvz[p]);
        const u64* w2 = (const u64*)(sWv1 + (16+p)*16);
        #pragma unroll
        for (int k=0;k<8;k++){ fma2_(vxa[k],mx,w2[k]); fma2_(vya[k],my,w2[k]); fma2_(vza[k],mz,w2[k]); }
    }

    // ---- coalesced message write: channel-major planes, slot index s ----
    float* mp = g_msg + s;
    #pragma unroll
    for (int k=0;k<8;k++){
        float g0 = sigmoidf_(s2[2*k]);
        float g1 = sigmoidf_(s2[2*k+1]);
        float x0,x1,y0,y1,z0,z1;
        upk2(vxa[k],x0,x1); upk2(vya[k],y0,y1); upk2(vza[k],z0,z1);
        mp[(size_t)(16+6*k+0)*NE] = x0*g0;
        mp[(size_t)(16+6*k+1)*NE] = y0*g0;
        mp[(size_t)(16+6*k+2)*NE] = z0*g0;
        mp[(size_t)(16+6*k+3)*NE] = x1*g1;
        mp[(size_t)(16+6*k+4)*NE] = y1*g1;
        mp[(size_t)(16+6*k+5)*NE] = z1*g1;
        mp[(size_t)(2*k+0)*NE]    = geluf_(s2[16+2*k]);
        mp[(size_t)(2*k+1)*NE]    = geluf_(s2[16+2*k+1]);
    }
    mp[(size_t)64*NE] = avx;
    mp[(size_t)65*NE] = avy;
    mp[(size_t)66*NE] = avz;
}

// ---------------- aggregation: contiguous per-node sums, fully coalesced ----------------
__global__ void __launch_bounds__(256) agg_kernel(){
    int n = blockIdx.x*256 + threadIdx.x;
    int c = blockIdx.y;
    if (n >= NN) return;
    int a = g_row[n], b = g_row[n+1];
    const float* p = g_msg + (size_t)c*NE;
    float sum = 0.f;
    for (int i=a;i<b;i++) sum += p[i];
    if (c < 16)      g_accS[n*16+c]      = sum;
    else if (c < 64) g_accV[n*48+(c-16)] = sum;
    else             g_accAv[n*3+(c-64)] = sum;
}

// ---------------- node kernel: thread-pair per node, channel-split ----------------
// NOTE: no early return before __shfl_xor_sync — ghost threads clamp n and skip stores.
__global__ void __launch_bounds__(256) node_kernel(
    const float* __restrict__ nWs, const float* __restrict__ nbs, const float* __restrict__ nWv,
    const float* __restrict__ fWs, const float* __restrict__ fbs, const float* __restrict__ fWv)
{
    // weight rows padded 17 -> 18 floats (8B-aligned u64 pair loads)
    __shared__ __align__(16) float sW[2*289*18];
    __shared__ __align__(16) float sV[2*289];
    __shared__ __align__(16) float sB[2*17];
    __shared__ __align__(16) float sF[256];
    __shared__ __align__(16) float sFb[16];
    __shared__ float sFv[1];
    int tid = threadIdx.x;
    for (int i=tid;i<2*289*17;i+=256){
        int b = i/(289*17); int r = i - b*289*17; int p = r/17; int q = r - p*17;
        sW[b*289*18 + p*18 + q] = nWs[i];
    }
    for (int i=tid;i<2*289;i+=256) sV[i]=nWv[i];
    if (tid<34) sB[tid]=nbs[tid];
    if (tid<256) sF[tid]=fWs[tid];
    if (tid<16) sFb[tid]=fbs[tid];
    if (tid==0) sFv[0]=fWv[0];
    __syncthreads();

    int id = blockIdx.x*256 + tid;
    bool valid = (id < 2*NN);
    int n  = valid ? (id >> 1) : (NN-1);   // clamp: ghost threads compute but never store
    int h  = id & 1;                       // channel half: h=0 -> sl[0..7], h=1 -> sl[8..15]

    int r0i = g_row[n], r1i = g_row[n+1];
    float cnt = (float)(r1i - r0i);
    float fsc = INV_NORM / fmaxf(cnt,1.0f);
    float ys[17];
    #pragma unroll
    for (int c=0;c<16;c++) ys[c] = g_accS[n*16+c]*fsc;
    ys[16] = (cnt>0.f) ? INV_NORM : 0.f;

    float nsv[16];
    #pragma unroll
    for (int a=0;a<16;a++) nsv[a]=g_s[n*16+a];
    float nvx=g_v[n*3+0], nvy=g_v[n*3+1], nvz=g_v[n*3+2];

    int hoff = 8*h;                 // float offset of this thread's channel half

    #pragma unroll 1
    for (int b=0;b<2;b++){
        const float* Wb = sW + b*289*18;
        const float* Vb = sV + b*289;
        u64 sl2[4];
        float sl16;
        {
            #pragma unroll
            for (int k=0;k<4;k++) sl2[k]=pk2(sB[b*17+hoff+2*k], sB[b*17+hoff+2*k+1]);
            sl16 = sB[b*17+16];
        }
        float wv[17];
        #pragma unroll
        for (int d=0;d<17;d++) wv[d]=0.f;

        // ss rows (split channel half per thread)
        for (int a=0;a<16;a++){
            float na = nsv[a];
            #pragma unroll
            for (int c=0;c<17;c++){
                float t = na*ys[c];
                u64 t2 = bc2(t);
                const u64* wr = (const u64*)(Wb + (a*17+c)*18 + hoff);
                #pragma unroll
                for (int k=0;k<4;k++) fma2_(sl2[k], t2, wr[k]);
                sl16  += t*Wb[(a*17+c)*18+16];
                wv[c] += na*Vb[a*17+c];
            }
        }

        // vv rows
        float vx=0.f, vy=0.f, vz=0.f;
        #pragma unroll
        for (int d=0;d<17;d++){
            float yx,yy,yz;
            if (d<16){ yx=g_accV[n*48+d*3+0]*fsc; yy=g_accV[n*48+d*3+1]*fsc; yz=g_accV[n*48+d*3+2]*fsc; }
            else     { yx=g_accAv[n*3+0]*fsc;     yy=g_accAv[n*3+1]*fsc;     yz=g_accAv[n*3+2]*fsc; }
            float t = nvx*yx+nvy*yy+nvz*yz;
            u64 t2 = bc2(t);
            const u64* wr = (const u64*)(Wb + (272+d)*18 + hoff);
            #pragma unroll
            for (int k=0;k<4;k++) fma2_(sl2[k], t2, wr[k]);
            sl16 += t*Wb[(272+d)*18+16];
            vx += yx*wv[d]; vy += yy*wv[d]; vz += yz*wv[d];
        }
        // vs rows
        float sc=0.f;
        #pragma unroll
        for (int c=0;c<17;c++) sc += ys[c]*Vb[272+c];
        vx += nvx*sc; vy += nvy*sc; vz += nvz*sc;

        float slh[8];
        #pragma unroll
        for (int k=0;k<4;k++) upk2(sl2[k], slh[2*k], slh[2*k+1]);

        // exchange: even thread owns sl[0..7] (gate + nsv[0..6]); odd owns sl[8..15],sl16 (nsv[7..15])
        float ex[9];
        if (h==0){
            ex[0] = sigmoidf_(slh[0]);
            #pragma unroll
            for (int k=1;k<8;k++) ex[k] = geluf_(slh[k]);
            ex[8] = 0.f;
        } else {
            #pragma unroll
            for (int k=0;k<8;k++) ex[k] = geluf_(slh[k]);
            ex[8] = geluf_(sl16);
        }
        float ot[9];
        #pragma unroll
        for (int k=0;k<9;k++) ot[k] = __shfl_xor_sync(0xffffffffu, ex[k], 1);

        float g;
        if (h==0){
            g = ex[0];
            #pragma unroll
            for (int k=0;k<7;k++) nsv[k]   = ex[k+1];
            #pragma unroll
            for (int k=0;k<8;k++) nsv[7+k] = ot[k];
            nsv[15] = ot[8];
        } else {
            g = ot[0];
            #pragma unroll
            for (int k=0;k<7;k++) nsv[k]   = ot[k+1];
            #pragma unroll
            for (int k=0;k<8;k++) nsv[7+k] = ex[k];
            nsv[15] = ex[8];
        }
        nvx = vx*g; nvy = vy*g; nvz = vz*g;
    }

    // final linear back to irreps_in + residual (this thread's channel half)
    u64 out2[4];
    {
        const u64* gs2 = (const u64*)(g_s + n*16 + hoff);
        const u64* fb2 = (const u64*)(sFb + hoff);
        #pragma unroll
        for (int k=0;k<4;k++){ out2[k]=gs2[k]; fma2_(out2[k], bc2(1.0f), fb2[k]); }
    }
    #pragma unroll
    for (int a=0;a<16;a++){
        u64 na2 = bc2(nsv[a]);
        const u64* w2 = (const u64*)(sF + a*16 + hoff);
        #pragma unroll
        for (int k=0;k<4;k++) fma2_(out2[k], na2, w2[k]);
    }
    if (valid){
        u64* gs2w = (u64*)(g_s + n*16 + hoff);
        #pragma unroll
        for (int k=0;k<4;k++) gs2w[k]=out2[k];
        if (h==0){
            float fv = sFv[0];
            g_v[n*3+0] += nvx*fv;
            g_v[n*3+1] += nvy*fv;
            g_v[n*3+2] += nvz*fv;
        }
    }
}

// ---------------- launch ----------------
extern "C" void kernel_launch(void* const* d_in, const int* in_sizes, int n_in,
                              void* d_out, int out_size)
{
    const float* node_s   = (const float*)d_in[0];
    const float* node_p   = (const float*)d_in[1];
    const int*   senders  = (const int*)d_in[2];
    const int*   receivers= (const int*)d_in[3];
    const float* eWs0 = (const float*)d_in[4];
    const float* ebs0 = (const float*)d_in[5];
    const float* eWv0 = (const float*)d_in[6];
    const float* eWs1 = (const float*)d_in[7];
    const float* ebs1 = (const float*)d_in[8];
    const float* eWv1 = (const float*)d_in[9];
    const float* nWs  = (const float*)d_in[10];
    const float* nbs  = (const float*)d_in[11];
    const float* nWv  = (const float*)d_in[12];
    const float* fWs  = (const float*)d_in[13];
    const float* fbs  = (const float*)d_in[14];
    const float* fWv  = (const float*)d_in[15];

    init_kernel<<<(NN*16+255)/256,256>>>(node_s, node_p);
    count_kernel<<<(NE+255)/256,256>>>(receivers);
    scan_kernel<<<1,1024>>>();
    scatter_kernel<<<(NE+255)/256,256>>>(senders, receivers);

    for (int t=0;t<3;t++){
        edge_kernel<<<(NE+127)/128,128>>>(
            eWs0 + t*34*32, ebs0 + t*32, eWv0 + t*34*16,
            eWs1 + t*32*32, ebs1 + t*32, eWv1 + t*32*16);
        agg_kernel<<<dim3((NN+255)/256, 67),256>>>();
        node_kernel<<<(2*NN+255)/256,256>>>(
            nWs + t*2*289*17, nbs + t*2*17, nWv + t*2*289,
            fWs + t*256, fbs + t*16, fWv + t);
    }
    pack_kernel<<<(NN+255)/256,256>>>((float*)d_out);
}